// round 1
// baseline (speedup 1.0000x reference)
#include <cuda_runtime.h>
#include <cuda_bf16.h>

#define BB 32
#define NPT 50
#define CC 85
#define HW0 4096
#define HW1 1024
#define HW2 256
#define TBL 4096

__device__ int d_winner[BB*(HW0+HW1+HW2)];
__device__ double d_acc;
__device__ unsigned int d_done;

__device__ __forceinline__ float clampf(float x){
    return fminf(fmaxf(x, -10.0f), 10.0f);
}

__global__ void k_init(){
    int i = blockIdx.x*blockDim.x + threadIdx.x;
    int n = BB*(HW0+HW1+HW2);
    int stride = gridDim.x*blockDim.x;
    for (; i < n; i += stride) d_winner[i] = -1;
    if (blockIdx.x == 0 && threadIdx.x == 0){ d_acc = 0.0; d_done = 0u; }
}

__global__ void k_scatter(const float* __restrict__ boxes){
    int p = blockIdx.x*blockDim.x + threadIdx.x;
    if (p >= BB*NPT) return;
    int b = p / NPT;
    float cx = boxes[p*4+0], cy = boxes[p*4+1];
    {
        int gi = min((int)(cx*64.0f), 63);
        int gj = min((int)(cy*64.0f), 63);
        atomicMax(&d_winner[b*HW0 + gj*64 + gi], p);
    }
    {
        int gi = min((int)(cx*32.0f), 31);
        int gj = min((int)(cy*32.0f), 31);
        atomicMax(&d_winner[BB*HW0 + b*HW1 + gj*32 + gi], p);
    }
    {
        int gi = min((int)(cx*16.0f), 15);
        int gj = min((int)(cy*16.0f), 15);
        atomicMax(&d_winner[BB*HW0 + BB*HW1 + b*HW2 + gj*16 + gi], p);
    }
}

__global__ void __launch_bounds__(256)
k_main(const float* __restrict__ p0, const float* __restrict__ p1,
       const float* __restrict__ p2, const float* __restrict__ boxes,
       const int* __restrict__ labels, float* __restrict__ out)
{
    __shared__ float tbl[TBL];
    __shared__ float red[256];

    // Build softplus table: x in [-10,10] mapped to idx 0..TBL-1
    for (int i = threadIdx.x; i < TBL; i += blockDim.x){
        float x = -10.0f + 20.0f * (float)i / (float)(TBL-1);
        tbl[i] = fmaxf(x, 0.0f) + log1pf(expf(-fabsf(x)));
    }
    __syncthreads();

    const int gtid = blockIdx.x*blockDim.x + threadIdx.x;
    const int stride = gridDim.x*blockDim.x;
    float master = 0.0f;

    // ---- Sparse corrections: one thread per (b, n) point ----
    if (gtid < BB*NPT){
        int p = gtid;
        int b = p / NPT;
        int n = p - b*NPT;
        const float4 bx = ((const float4*)boxes)[p];
        int lab = labels[p];
        const float* PS[3] = {p0, p1, p2};
        const int wdim[3] = {64, 32, 16};
        const int woffb[3] = {0, BB*HW0, BB*HW0 + BB*HW1};
        #pragma unroll
        for (int s = 0; s < 3; s++){
            int w = wdim[s];
            int hw = w*w;
            float fw = (float)w;
            float gx = bx.x*fw, gy = bx.y*fw;
            int gi = min((int)gx, w-1);
            int gj = min((int)gy, w-1);
            int cell = gj*w + gi;
            const float* P = PS[s];
            float fhw = (float)hw;
            float wb = 5.0f/(128.0f*fhw), wo = 1.0f/(32.0f*fhw), wc = 1.0f/(2560.0f*fhw);
            int widx = woffb[s] + b*hw + cell;
            bool iswin = (d_winner[widx] == p);
            bool clsDo = iswin;
            if (!iswin){
                // there exists a later point in this cell; dedup cls on (cell,label)
                clsDo = true;
                for (int q = n+1; q < NPT; q++){
                    int pq = b*NPT + q;
                    float qx = boxes[pq*4]*fw;
                    float qy = boxes[pq*4+1]*fw;
                    int qgi = min((int)qx, w-1);
                    int qgj = min((int)qy, w-1);
                    if (qgi == gi && qgj == gj && labels[pq] == lab){ clsDo = false; break; }
                }
            }
            int base = (b*CC)*hw + cell;
            if (iswin){
                float po = clampf(P[base + 4*hw]);
                master -= wo*po;
                float t0 = gx - (float)gi, t1 = gy - (float)gj, t2 = bx.z, t3 = bx.w;
                float pb0 = clampf(P[base + 0*hw]);
                float pb1 = clampf(P[base + 1*hw]);
                float pb2 = clampf(P[base + 2*hw]);
                float pb3 = clampf(P[base + 3*hw]);
                master += wb*((t0*t0 - 2.0f*pb0*t0) + (t1*t1 - 2.0f*pb1*t1)
                            + (t2*t2 - 2.0f*pb2*t2) + (t3*t3 - 2.0f*pb3*t3));
            }
            if (clsDo){
                float pc = clampf(P[base + (5+lab)*hw]);
                master -= wc*pc;
            }
        }
    }

    // ---- Dense streaming baseline ----
    const float KS   = (float)(TBL-1) / 20.0f;
    const float KOFF = 10.0f * KS;
    const float* PP[3] = {p0, p1, p2};
    const int n4s[3] = {BB*CC*HW0/4, BB*CC*HW1/4, BB*CC*HW2/4};
    const int shf[3] = {10, 8, 6};
    const float hwf[3] = {(float)HW0, (float)HW1, (float)HW2};

    #pragma unroll
    for (int s = 0; s < 3; s++){
        const float4* __restrict__ P4 = (const float4*)PP[s];
        const int n4 = n4s[s];
        const int sh = shf[s];
        float accB = 0.0f, accO = 0.0f, accC = 0.0f;
        for (int v = gtid; v < n4; v += stride){
            float4 x = P4[v];
            int c = (v >> sh) % 85;   // channel; warp-uniform since hw/4 >= 64
            if (c < 4){
                float a0 = clampf(x.x), a1 = clampf(x.y);
                float a2 = clampf(x.z), a3 = clampf(x.w);
                accB += a0*a0 + a1*a1 + a2*a2 + a3*a3;
            } else {
                int i0 = min(max(__float2int_rn(fmaf(x.x, KS, KOFF)), 0), TBL-1);
                int i1 = min(max(__float2int_rn(fmaf(x.y, KS, KOFF)), 0), TBL-1);
                int i2 = min(max(__float2int_rn(fmaf(x.z, KS, KOFF)), 0), TBL-1);
                int i3 = min(max(__float2int_rn(fmaf(x.w, KS, KOFF)), 0), TBL-1);
                float sum = tbl[i0] + tbl[i1] + tbl[i2] + tbl[i3];
                if (c == 4) accO += sum; else accC += sum;
            }
        }
        float fhw = hwf[s];
        master += (5.0f/(128.0f*fhw))*accB + (1.0f/(32.0f*fhw))*accO
                + (1.0f/(2560.0f*fhw))*accC;
    }

    // ---- Block reduction + global accumulate + last-block finalize ----
    red[threadIdx.x] = master;
    __syncthreads();
    for (int o = 128; o > 0; o >>= 1){
        if (threadIdx.x < o) red[threadIdx.x] += red[threadIdx.x + o];
        __syncthreads();
    }
    if (threadIdx.x == 0){
        atomicAdd(&d_acc, (double)red[0]);
        __threadfence();
        unsigned int done = atomicAdd(&d_done, 1u);
        if (done == gridDim.x - 1){
            double tot = atomicAdd(&d_acc, 0.0);  // fully accumulated, coherent read
            float r = (float)(tot / 3.0);
            r = fminf(fmaxf(r, 0.0f), 1.0e6f);
            out[0] = r;
        }
    }
}

extern "C" void kernel_launch(void* const* d_in, const int* in_sizes, int n_in,
                              void* d_out, int out_size)
{
    const float* p0     = (const float*)d_in[0];
    const float* p1     = (const float*)d_in[1];
    const float* p2     = (const float*)d_in[2];
    const float* boxes  = (const float*)d_in[3];
    const int*   labels = (const int*)d_in[4];
    float* out = (float*)d_out;

    k_init<<<672, 256>>>();
    k_scatter<<<(BB*NPT + 255)/256, 256>>>(boxes);
    k_main<<<1184, 256>>>(p0, p1, p2, boxes, labels, out);
}

// round 2
// speedup vs baseline: 1.8582x; 1.8582x over previous
#include <cuda_runtime.h>
#include <cuda_bf16.h>

#define BB 32
#define NPT 50
#define CC 85
#define TBL 4096

// grid partition: blocks per scale (proportional to 16:4:1)
#define GRID_TOTAL 592
#define B0 451
#define B1 113
#define B2 28

__device__ double d_acc = 0.0;
__device__ unsigned int d_done = 0u;

__device__ __forceinline__ float clampf(float x){
    return fminf(fmaxf(x, -10.0f), 10.0f);
}

// softplus table lookup: x -> nearest of 4096 samples on [-10,10]
// t = sat(x/20 + 0.5) in [0,1];  y = t*4095 + (2^21 + 0.375)
// float y has ulp 0.25 in [2^21, 2^21+4096); low mantissa bits = (y-2^21)*4.
// AND 0x3FFC ==> byte offset 4*floor(v+0.5) (the +0.375 shifts the floor to
// round-to-nearest). All ops are full-rate fixed-latency (no F2I, no IMNMX).
__device__ __forceinline__ float sp_lookup(const float* tbl, float x){
    float t = __saturatef(__fmaf_rn(x, 0.05f, 0.5f));
    float y = __fmaf_rn(t, 4095.0f, 2097152.375f);
    int off = __float_as_int(y) & 0x3FFC;
    return *reinterpret_cast<const float*>(reinterpret_cast<const char*>(tbl) + off);
}

template<int HW>
__device__ __forceinline__ float dense_scale(const float* __restrict__ P,
                                             int ltid, int lstride,
                                             const float* tbl)
{
    const float4* __restrict__ P4 = reinterpret_cast<const float4*>(P);
    const int batchF4 = CC*HW/4;

    // ---- softplus region: channels 4..84, weight wc (ch4 delta added below) ----
    float accS = 0.0f;
    {
        const int spf4 = 81*HW/4;          // float4 per batch in softplus region
        const int n = BB*spf4;
        int v = ltid;
        for (; v + 3*lstride < n; v += 4*lstride){
            #pragma unroll
            for (int j = 0; j < 4; j++){
                int vv = v + j*lstride;
                int b = vv / spf4;          // compile-time divisor -> magic mul
                int r = vv - b*spf4;
                float4 x = P4[b*batchF4 + HW + r];   // +HW f4 == +4*HW floats
                accS += sp_lookup(tbl, x.x) + sp_lookup(tbl, x.y)
                      + sp_lookup(tbl, x.z) + sp_lookup(tbl, x.w);
            }
        }
        for (; v < n; v += lstride){
            int b = v / spf4;
            int r = v - b*spf4;
            float4 x = P4[b*batchF4 + HW + r];
            accS += sp_lookup(tbl, x.x) + sp_lookup(tbl, x.y)
                  + sp_lookup(tbl, x.z) + sp_lookup(tbl, x.w);
        }
    }

    // ---- box region: channels 0..3, sum clamp(x)^2 ----
    float accB = 0.0f;
    {
        const int n = BB*HW;               // float4 count (4*HW floats / batch)
        for (int v = ltid; v < n; v += lstride){
            int b = v / HW;                // power of 2 -> shift
            int r = v % HW;
            float4 x = P4[b*batchF4 + r];
            float a;
            a = clampf(x.x); accB = __fmaf_rn(a, a, accB);
            a = clampf(x.y); accB = __fmaf_rn(a, a, accB);
            a = clampf(x.z); accB = __fmaf_rn(a, a, accB);
            a = clampf(x.w); accB = __fmaf_rn(a, a, accB);
        }
    }

    // ---- obj extra: re-read channel 4 with weight (wo - wc) ----
    float accO = 0.0f;
    {
        const int pf4 = HW/4;
        const int n = BB*pf4;
        for (int v = ltid; v < n; v += lstride){
            int b = v / pf4;
            int r = v % pf4;
            float4 x = P4[b*batchF4 + HW + r];
            accO += sp_lookup(tbl, x.x) + sp_lookup(tbl, x.y)
                  + sp_lookup(tbl, x.z) + sp_lookup(tbl, x.w);
        }
    }

    const float fhw = (float)HW;
    return (5.0f/(128.0f*fhw))*accB
         + (1.0f/(2560.0f*fhw))*accS
         + (79.0f/(2560.0f*fhw))*accO;
}

__device__ __forceinline__ float sparse_corr(int p,
        const float* __restrict__ p0, const float* __restrict__ p1,
        const float* __restrict__ p2, const float* __restrict__ boxes,
        const int* __restrict__ labels)
{
    int b = p / NPT, n = p - (p/NPT)*NPT;
    float4 bx = reinterpret_cast<const float4*>(boxes)[p];
    int lab = labels[p];
    const int wd[3] = {64, 32, 16};
    const float* P[3] = {p0, p1, p2};
    int gi[3], gj[3];
    bool iswin[3] = {true, true, true};
    bool clsdo[3] = {true, true, true};
    #pragma unroll
    for (int s = 0; s < 3; s++){
        gi[s] = min((int)(bx.x*(float)wd[s]), wd[s]-1);
        gj[s] = min((int)(bx.y*(float)wd[s]), wd[s]-1);
    }
    // winner/dedup scan: p wins its cell iff no later q maps to the same cell;
    // cls contributes iff no later q has same cell AND same label.
    for (int q = n+1; q < NPT; q++){
        int pq = b*NPT + q;
        float qx = boxes[pq*4], qy = boxes[pq*4+1];
        int ql = labels[pq];
        #pragma unroll
        for (int s = 0; s < 3; s++){
            int qi = min((int)(qx*(float)wd[s]), wd[s]-1);
            int qj = min((int)(qy*(float)wd[s]), wd[s]-1);
            if (qi == gi[s] && qj == gj[s]){
                iswin[s] = false;
                if (ql == lab) clsdo[s] = false;
            }
        }
    }
    float m = 0.0f;
    #pragma unroll
    for (int s = 0; s < 3; s++){
        int w = wd[s], hw = w*w;
        float fhw = (float)hw;
        int base = b*CC*hw + gj[s]*w + gi[s];
        if (iswin[s]){
            float gx = bx.x*(float)w, gy = bx.y*(float)w;
            float t0 = gx - (float)gi[s], t1 = gy - (float)gj[s];
            float t2 = bx.z, t3 = bx.w;
            float pb0 = clampf(P[s][base]);
            float pb1 = clampf(P[s][base + hw]);
            float pb2 = clampf(P[s][base + 2*hw]);
            float pb3 = clampf(P[s][base + 3*hw]);
            m += (5.0f/(128.0f*fhw)) * ((t0*t0 - 2.0f*pb0*t0) + (t1*t1 - 2.0f*pb1*t1)
                                      + (t2*t2 - 2.0f*pb2*t2) + (t3*t3 - 2.0f*pb3*t3));
            m -= (1.0f/(32.0f*fhw)) * clampf(P[s][base + 4*hw]);
        }
        if (clsdo[s]){
            m -= (1.0f/(2560.0f*fhw)) * clampf(P[s][base + (5+lab)*hw]);
        }
    }
    return m;
}

__global__ void __launch_bounds__(256, 4)
k_all(const float* __restrict__ p0, const float* __restrict__ p1,
      const float* __restrict__ p2, const float* __restrict__ boxes,
      const int* __restrict__ labels, float* __restrict__ out)
{
    __shared__ float tbl[TBL];
    __shared__ float red[8];

    // Build softplus table with fast intrinsics (abs err ~1e-6, table bin 5e-3)
    for (int i = threadIdx.x; i < TBL; i += blockDim.x){
        float x = -10.0f + 20.0f * (float)i * (1.0f/4095.0f);
        float e = __expf(-fabsf(x));
        tbl[i] = fmaxf(x, 0.0f) + __logf(1.0f + e);
    }
    __syncthreads();

    const int bid = blockIdx.x;
    const int gtid = bid*256 + threadIdx.x;

    float master = 0.0f;

    // Sparse corrections: 1600 points, one thread each (live in scale-0 blocks)
    if (gtid < BB*NPT){
        master += sparse_corr(gtid, p0, p1, p2, boxes, labels);
    }

    // Dense streaming, blocks partitioned by scale
    if (bid < B0){
        int ltid = bid*256 + threadIdx.x;
        master += dense_scale<4096>(p0, ltid, B0*256, tbl);
    } else if (bid < B0 + B1){
        int ltid = (bid - B0)*256 + threadIdx.x;
        master += dense_scale<1024>(p1, ltid, B1*256, tbl);
    } else {
        int ltid = (bid - B0 - B1)*256 + threadIdx.x;
        master += dense_scale<256>(p2, ltid, B2*256, tbl);
    }

    // Reduction: warp shuffle -> block -> global double atomic
    unsigned mask = 0xffffffffu;
    for (int o = 16; o; o >>= 1) master += __shfl_down_sync(mask, master, o);
    if ((threadIdx.x & 31) == 0) red[threadIdx.x >> 5] = master;
    __syncthreads();
    if (threadIdx.x < 32){
        float v = (threadIdx.x < 8) ? red[threadIdx.x] : 0.0f;
        for (int o = 4; o; o >>= 1) v += __shfl_down_sync(mask, v, o);
        if (threadIdx.x == 0){
            atomicAdd(&d_acc, (double)v);
            __threadfence();
            unsigned done = atomicAdd(&d_done, 1u);
            if (done == gridDim.x - 1){
                double tot = atomicAdd(&d_acc, 0.0);   // coherent read
                float r = (float)(tot * (1.0/3.0));
                r = fminf(fmaxf(r, 0.0f), 1.0e6f);
                out[0] = r;
                // self-reset for next graph replay
                d_acc = 0.0;
                __threadfence();
                d_done = 0u;
            }
        }
    }
}

extern "C" void kernel_launch(void* const* d_in, const int* in_sizes, int n_in,
                              void* d_out, int out_size)
{
    const float* p0     = (const float*)d_in[0];
    const float* p1     = (const float*)d_in[1];
    const float* p2     = (const float*)d_in[2];
    const float* boxes  = (const float*)d_in[3];
    const int*   labels = (const int*)d_in[4];
    float* out = (float*)d_out;

    k_all<<<GRID_TOTAL, 256>>>(p0, p1, p2, boxes, labels, out);
}

// round 3
// speedup vs baseline: 1.8638x; 1.0030x over previous
#include <cuda_runtime.h>
#include <cuda_bf16.h>

#define BB 32
#define NPT 50
#define CC 85
#define TBL 2048

// Static block partition (grid = 586 < 148*4 = one wave)
#define NB_S0 416   // 13 blocks per batch, scale0 softplus region
#define NB_S1 96    // 3 per batch, scale1
#define NB_S2 32    // 1 per batch, scale2 (+sparse corrections)
#define NB_MA 32    // scale0 box+ch4, one batch each
#define NB_MB 8     // scale1 box+ch4, 4 batches each
#define NB_MC 2     // scale2 box+ch4, 16 batches each
#define GRID_TOTAL (NB_S0+NB_S1+NB_S2+NB_MA+NB_MB+NB_MC)

__device__ double d_acc = 0.0;
__device__ unsigned int d_done = 0u;

__device__ __forceinline__ float clampf(float x){
    return fminf(fmaxf(x, -10.0f), 10.0f);
}

// softplus nearest-neighbor lookup, 2048 samples on [-10,10].
// t = sat(x/20+0.5); y = t*2047 + (2^21 + 0.375); in [2^21,2^22) float ulp
// is 0.25, so low mantissa bits = 4*(y-2^21); AND 0x1FFC yields byte offset
// 4*round(t*2047). All full-rate fixed-latency ops (no F2I/IMNMX).
__device__ __forceinline__ float sp_lookup(const float* tbl, float x){
    float t = __saturatef(__fmaf_rn(x, 0.05f, 0.5f));
    float y = __fmaf_rn(t, 2047.0f, 2097152.375f);
    int off = __float_as_int(y) & 0x1FFC;
    return *reinterpret_cast<const float*>(reinterpret_cast<const char*>(tbl) + off);
}

// Sum softplus over n float4 starting at base; threads stride 256.
__device__ __forceinline__ float sum_sp(const float4* __restrict__ base, int n,
                                        const float* tbl)
{
    float acc = 0.0f;
    int v = threadIdx.x;
    for (; v + 768 < n; v += 1024){
        float4 a = base[v];
        float4 b = base[v + 256];
        float4 c = base[v + 512];
        float4 d = base[v + 768];
        acc += (sp_lookup(tbl,a.x)+sp_lookup(tbl,a.y))+(sp_lookup(tbl,a.z)+sp_lookup(tbl,a.w));
        acc += (sp_lookup(tbl,b.x)+sp_lookup(tbl,b.y))+(sp_lookup(tbl,b.z)+sp_lookup(tbl,b.w));
        acc += (sp_lookup(tbl,c.x)+sp_lookup(tbl,c.y))+(sp_lookup(tbl,c.z)+sp_lookup(tbl,c.w));
        acc += (sp_lookup(tbl,d.x)+sp_lookup(tbl,d.y))+(sp_lookup(tbl,d.z)+sp_lookup(tbl,d.w));
    }
    for (; v < n; v += 256){
        float4 a = base[v];
        acc += (sp_lookup(tbl,a.x)+sp_lookup(tbl,a.y))+(sp_lookup(tbl,a.z)+sp_lookup(tbl,a.w));
    }
    return acc;
}

// Sum clamp(x)^2 over n float4 starting at base.
__device__ __forceinline__ float sum_sq(const float4* __restrict__ base, int n)
{
    float acc = 0.0f;
    int v = threadIdx.x;
    for (; v + 768 < n; v += 1024){
        #pragma unroll
        for (int j = 0; j < 4; j++){
            float4 a = base[v + j*256];
            float q;
            q = clampf(a.x); acc = __fmaf_rn(q,q,acc);
            q = clampf(a.y); acc = __fmaf_rn(q,q,acc);
            q = clampf(a.z); acc = __fmaf_rn(q,q,acc);
            q = clampf(a.w); acc = __fmaf_rn(q,q,acc);
        }
    }
    for (; v < n; v += 256){
        float4 a = base[v];
        float q;
        q = clampf(a.x); acc = __fmaf_rn(q,q,acc);
        q = clampf(a.y); acc = __fmaf_rn(q,q,acc);
        q = clampf(a.z); acc = __fmaf_rn(q,q,acc);
        q = clampf(a.w); acc = __fmaf_rn(q,q,acc);
    }
    return acc;
}

__device__ __forceinline__ float sparse_corr(int p,
        const float* __restrict__ p0, const float* __restrict__ p1,
        const float* __restrict__ p2, const float* __restrict__ boxes,
        const int* __restrict__ labels)
{
    int b = p / NPT, n = p - b*NPT;
    float4 bx = reinterpret_cast<const float4*>(boxes)[p];
    int lab = labels[p];
    const int wd[3] = {64, 32, 16};
    const float* P[3] = {p0, p1, p2};
    int gi[3], gj[3];
    bool iswin[3] = {true, true, true};
    bool clsdo[3] = {true, true, true};
    #pragma unroll
    for (int s = 0; s < 3; s++){
        gi[s] = min((int)(bx.x*(float)wd[s]), wd[s]-1);
        gj[s] = min((int)(bx.y*(float)wd[s]), wd[s]-1);
    }
    // p wins its cell iff no later q maps to same cell; cls contributes iff
    // no later q has same cell AND same label.
    for (int q = n+1; q < NPT; q++){
        int pq = b*NPT + q;
        float qx = boxes[pq*4], qy = boxes[pq*4+1];
        int ql = labels[pq];
        #pragma unroll
        for (int s = 0; s < 3; s++){
            int qi = min((int)(qx*(float)wd[s]), wd[s]-1);
            int qj = min((int)(qy*(float)wd[s]), wd[s]-1);
            if (qi == gi[s] && qj == gj[s]){
                iswin[s] = false;
                if (ql == lab) clsdo[s] = false;
            }
        }
    }
    float m = 0.0f;
    #pragma unroll
    for (int s = 0; s < 3; s++){
        int w = wd[s], hw = w*w;
        float fhw = (float)hw;
        int base = b*CC*hw + gj[s]*w + gi[s];
        if (iswin[s]){
            float gx = bx.x*(float)w, gy = bx.y*(float)w;
            float t0 = gx - (float)gi[s], t1 = gy - (float)gj[s];
            float t2 = bx.z, t3 = bx.w;
            float pb0 = clampf(P[s][base]);
            float pb1 = clampf(P[s][base + hw]);
            float pb2 = clampf(P[s][base + 2*hw]);
            float pb3 = clampf(P[s][base + 3*hw]);
            m += (5.0f/(128.0f*fhw)) * ((t0*t0 - 2.0f*pb0*t0) + (t1*t1 - 2.0f*pb1*t1)
                                      + (t2*t2 - 2.0f*pb2*t2) + (t3*t3 - 2.0f*pb3*t3));
            m -= (1.0f/(32.0f*fhw)) * clampf(P[s][base + 4*hw]);
        }
        if (clsdo[s]){
            m -= (1.0f/(2560.0f*fhw)) * clampf(P[s][base + (5+lab)*hw]);
        }
    }
    return m;
}

__global__ void __launch_bounds__(256, 4)
k_all(const float* __restrict__ p0, const float* __restrict__ p1,
      const float* __restrict__ p2, const float* __restrict__ boxes,
      const int* __restrict__ labels, float* __restrict__ out)
{
    __shared__ float tbl[TBL];
    __shared__ float red[8];

    for (int i = threadIdx.x; i < TBL; i += 256){
        float x = -10.0f + 20.0f * (float)i * (1.0f/2047.0f);
        tbl[i] = fmaxf(x, 0.0f) + __logf(1.0f + __expf(-fabsf(x)));
    }
    __syncthreads();

    const int bid = blockIdx.x;
    float master = 0.0f;

    if (bid < NB_S0){
        // scale0 softplus region (ch 4..84), 13 blocks/batch
        int b = bid / 13, j = bid - b*13;
        const int L = 81*4096/4;                 // 82944 f4 per batch
        int lo = (int)(((long long)L * j) / 13);
        int hi = (int)(((long long)L * (j+1)) / 13);
        const float4* base = (const float4*)p0 + b*(CC*4096/4) + 4096 + lo;
        master += (1.0f/(2560.0f*4096.0f)) * sum_sp(base, hi - lo, tbl);
    } else if (bid < NB_S0 + NB_S1){
        // scale1 softplus region, 3 blocks/batch (20736/3 = 6912 exact)
        int idx = bid - NB_S0;
        int b = idx / 3, j = idx - b*3;
        const float4* base = (const float4*)p1 + b*(CC*1024/4) + 1024 + j*6912;
        master += (1.0f/(2560.0f*1024.0f)) * sum_sp(base, 6912, tbl);
    } else if (bid < NB_S0 + NB_S1 + NB_S2){
        // scale2 softplus region, 1 block/batch, plus that batch's sparse pts
        int b = bid - (NB_S0 + NB_S1);
        if (threadIdx.x < NPT)
            master += sparse_corr(b*NPT + threadIdx.x, p0, p1, p2, boxes, labels);
        const float4* base = (const float4*)p2 + b*(CC*256/4) + 256;
        master += (1.0f/(2560.0f*256.0f)) * sum_sp(base, 5184, tbl);
    } else if (bid < NB_S0 + NB_S1 + NB_S2 + NB_MA){
        // scale0 box (sq) + ch4 extra (wo-wc), one batch
        int b = bid - (NB_S0 + NB_S1 + NB_S2);
        const float4* base = (const float4*)p0 + b*(CC*4096/4);
        master += (5.0f/(128.0f*4096.0f))   * sum_sq(base, 4096);
        master += (79.0f/(2560.0f*4096.0f)) * sum_sp(base + 4096, 1024, tbl);
    } else if (bid < NB_S0 + NB_S1 + NB_S2 + NB_MA + NB_MB){
        // scale1 box + ch4 extra, 4 batches
        int m = bid - (NB_S0 + NB_S1 + NB_S2 + NB_MA);
        #pragma unroll
        for (int k = 0; k < 4; k++){
            int b = 4*m + k;
            const float4* base = (const float4*)p1 + b*(CC*1024/4);
            master += (5.0f/(128.0f*1024.0f))   * sum_sq(base, 1024);
            master += (79.0f/(2560.0f*1024.0f)) * sum_sp(base + 1024, 256, tbl);
        }
    } else {
        // scale2 box + ch4 extra, 16 batches
        int m = bid - (NB_S0 + NB_S1 + NB_S2 + NB_MA + NB_MB);
        for (int k = 0; k < 16; k++){
            int b = 16*m + k;
            const float4* base = (const float4*)p2 + b*(CC*256/4);
            master += (5.0f/(128.0f*256.0f))   * sum_sq(base, 256);
            master += (79.0f/(2560.0f*256.0f)) * sum_sp(base + 256, 64, tbl);
        }
    }

    // warp -> block -> global reduction
    unsigned mask = 0xffffffffu;
    for (int o = 16; o; o >>= 1) master += __shfl_down_sync(mask, master, o);
    if ((threadIdx.x & 31) == 0) red[threadIdx.x >> 5] = master;
    __syncthreads();
    if (threadIdx.x < 32){
        float v = (threadIdx.x < 8) ? red[threadIdx.x] : 0.0f;
        for (int o = 4; o; o >>= 1) v += __shfl_down_sync(mask, v, o);
        if (threadIdx.x == 0){
            atomicAdd(&d_acc, (double)v);
            __threadfence();
            unsigned done = atomicAdd(&d_done, 1u);
            if (done == gridDim.x - 1){
                double tot = atomicAdd(&d_acc, 0.0);   // coherent read
                float r = (float)(tot * (1.0/3.0));
                r = fminf(fmaxf(r, 0.0f), 1.0e6f);
                out[0] = r;
                d_acc = 0.0;            // self-reset for graph replay
                __threadfence();
                d_done = 0u;
            }
        }
    }
}

extern "C" void kernel_launch(void* const* d_in, const int* in_sizes, int n_in,
                              void* d_out, int out_size)
{
    const float* p0     = (const float*)d_in[0];
    const float* p1     = (const float*)d_in[1];
    const float* p2     = (const float*)d_in[2];
    const float* boxes  = (const float*)d_in[3];
    const int*   labels = (const int*)d_in[4];
    float* out = (float*)d_out;

    k_all<<<GRID_TOTAL, 256>>>(p0, p1, p2, boxes, labels, out);
}